// round 2
// baseline (speedup 1.0000x reference)
#include <cuda_runtime.h>

#define IMD 224
#define HWPX (IMD * IMD)

// Tile: 32 x-values (slow image dim of p) x 32 y-values (fast dim of p).
// Phase 1: coalesced loads of C0,C1,M1,M2 (consecutive threads -> consecutive y).
// Phase 2: threads remapped x-fast so gather index ind = nx + 224*ny is
//          coalesced across the warp (nx fast in memory).
// Phase 3: outputs staged in smem (reusing the input planes) and stored
//          coalesced y-fast.
__global__ __launch_bounds__(256, 2) void vm_kernel(
    const float* __restrict__ im1, const float* __restrict__ im2,
    const float* __restrict__ C,   const float* __restrict__ M1,
    const float* __restrict__ M2,  float* __restrict__ out)
{
    __shared__ float sA[32][33];  // C0  -> later out c0
    __shared__ float sB[32][33];  // C1  -> later out c1
    __shared__ float sD[32][33];  // M1  -> later out c2
    __shared__ float sE[32][33];  // M2

    const int tid = threadIdx.x;
    const int n  = blockIdx.z;
    const int x0 = blockIdx.y * 32;
    const int y0 = blockIdx.x * 32;

    const float* __restrict__ Cb0 = C  + (size_t)n * 2 * HWPX;
    const float* __restrict__ Cb1 = Cb0 + HWPX;
    const float* __restrict__ M1b = M1 + (size_t)n * HWPX;
    const float* __restrict__ M2b = M2 + (size_t)n * HWPX;
    const float* __restrict__ I1b = im1 + (size_t)n * 3 * HWPX;
    const float* __restrict__ I2b = im2 + (size_t)n * 3 * HWPX;

    // ---- Phase 1: coalesced tile load ----
#pragma unroll
    for (int k = 0; k < 4; k++) {
        int l  = tid + k * 256;
        int dx = l >> 5;
        int dy = l & 31;
        int g  = (x0 + dx) * IMD + (y0 + dy);
        sA[dx][dy] = Cb0[g];
        sB[dx][dy] = Cb1[g];
        sD[dx][dy] = M1b[g];
        sE[dx][dy] = M2b[g];
    }
    __syncthreads();

    // ---- Phase 2: x-fast compute ----
    const int dx = tid & 31;        // lane -> x (gathers coalesced)
    const int wp = tid >> 5;        // warp 0..7
    float res[4][3];

#pragma unroll
    for (int k = 0; k < 4; k++) {
        const int dy = wp + k * 8;
        const float c0 = sA[dx][dy];
        const float c1 = sB[dx][dy];
        const float m1 = sD[dx][dy];
        const float m2 = sE[dx][dy];
        const float xf = (float)(x0 + dx);
        const float yf = (float)(y0 + dy);

        // --- sample im1 at (x + c0, y + c1) ---
        {
            float px = xf + c0, py = yf + c1;
            float fx = floorf(px), cx = ceilf(px);
            float fy = floorf(py), cy = ceilf(py);
            float wfx = 1.0f - (px - fx), wcx = 1.0f - (cx - px);
            float wfy = 1.0f - (py - fy), wcy = 1.0f - (cy - py);
            int i00 = (int)fx + IMD * (int)fy;
            int i10 = (int)cx + IMD * (int)fy;
            int i01 = (int)fx + IMD * (int)cy;
            int i11 = (int)cx + IMD * (int)cy;
            i00 = min(max(i00, 0), HWPX - 1);
            i10 = min(max(i10, 0), HWPX - 1);
            i01 = min(max(i01, 0), HWPX - 1);
            i11 = min(max(i11, 0), HWPX - 1);
            float w00 = wfx * wfy, w10 = wcx * wfy;
            float w01 = wfx * wcy, w11 = wcx * wcy;
#pragma unroll
            for (int c = 0; c < 3; c++) {
                const float* pc = I1b + c * HWPX;
                float v = ((w00 * __ldg(pc + i00) + w10 * __ldg(pc + i10))
                          + w01 * __ldg(pc + i01)) + w11 * __ldg(pc + i11);
                res[k][c] = v * m1;
            }
        }
        // --- sample im2 at (x - c0, y - c1) ---
        {
            float px = xf - c0, py = yf - c1;
            float fx = floorf(px), cx = ceilf(px);
            float fy = floorf(py), cy = ceilf(py);
            float wfx = 1.0f - (px - fx), wcx = 1.0f - (cx - px);
            float wfy = 1.0f - (py - fy), wcy = 1.0f - (cy - py);
            int i00 = (int)fx + IMD * (int)fy;
            int i10 = (int)cx + IMD * (int)fy;
            int i01 = (int)fx + IMD * (int)cy;
            int i11 = (int)cx + IMD * (int)cy;
            i00 = min(max(i00, 0), HWPX - 1);
            i10 = min(max(i10, 0), HWPX - 1);
            i01 = min(max(i01, 0), HWPX - 1);
            i11 = min(max(i11, 0), HWPX - 1);
            float w00 = wfx * wfy, w10 = wcx * wfy;
            float w01 = wfx * wcy, w11 = wcx * wcy;
#pragma unroll
            for (int c = 0; c < 3; c++) {
                const float* pc = I2b + c * HWPX;
                float v = ((w00 * __ldg(pc + i00) + w10 * __ldg(pc + i10))
                          + w01 * __ldg(pc + i01)) + w11 * __ldg(pc + i11);
                res[k][c] += v * m2;
            }
        }
    }

    // Each (dx,dy) cell is read and written only by its owner thread in
    // phase 2, so no barrier is needed before the overwrite.
#pragma unroll
    for (int k = 0; k < 4; k++) {
        const int dy = wp + k * 8;
        sA[dx][dy] = res[k][0];
        sB[dx][dy] = res[k][1];
        sD[dx][dy] = res[k][2];
    }
    __syncthreads();

    // ---- Phase 3: coalesced store ----
    float* __restrict__ ob = out + (size_t)n * 3 * HWPX;
#pragma unroll
    for (int k = 0; k < 4; k++) {
        int l  = tid + k * 256;
        int ddx = l >> 5;
        int ddy = l & 31;
        int g  = (x0 + ddx) * IMD + (y0 + ddy);
        ob[g]            = sA[ddx][ddy];
        ob[HWPX + g]     = sB[ddx][ddy];
        ob[2 * HWPX + g] = sD[ddx][ddy];
    }
}

extern "C" void kernel_launch(void* const* d_in, const int* in_sizes, int n_in,
                              void* d_out, int out_size)
{
    const float* im1 = (const float*)d_in[0];
    const float* im2 = (const float*)d_in[1];
    const float* C   = (const float*)d_in[2];
    const float* M1  = (const float*)d_in[3];
    const float* M2  = (const float*)d_in[4];
    float* out = (float*)d_out;

    dim3 grid(IMD / 32, IMD / 32, 64);  // (7, 7, 64)
    vm_kernel<<<grid, 256>>>(im1, im2, C, M1, M2, out);
}

// round 4
// speedup vs baseline: 1.1576x; 1.1576x over previous
#include <cuda_runtime.h>

#define IMD 224
#define HWPX (IMD * IMD)

// Tile: 32 x-values (slow image dim of p) x 32 y-values (fast dim of p).
// Phase 1: coalesced loads of C0,C1,M1,M2 (consecutive threads -> consecutive y).
// Phase 2: threads remapped x-fast so gather index ind = nx + 224*ny is
//          coalesced across the warp (nx fast in memory). Results written
//          straight back to the (owner-private) smem cells per k-slice.
// Phase 3: outputs stored coalesced y-fast.
__global__ __launch_bounds__(256, 4) void vm_kernel(
    const float* __restrict__ im1, const float* __restrict__ im2,
    const float* __restrict__ C,   const float* __restrict__ M1,
    const float* __restrict__ M2,  float* __restrict__ out)
{
    __shared__ float sA[32][33];  // C0  -> out c0
    __shared__ float sB[32][33];  // C1  -> out c1
    __shared__ float sD[32][33];  // M1  -> out c2
    __shared__ float sE[32][33];  // M2

    const int tid = threadIdx.x;
    const int n  = blockIdx.z;
    const int x0 = blockIdx.y * 32;
    const int y0 = blockIdx.x * 32;

    const float* __restrict__ Cb0 = C  + (size_t)n * 2 * HWPX;
    const float* __restrict__ Cb1 = Cb0 + HWPX;
    const float* __restrict__ M1b = M1 + (size_t)n * HWPX;
    const float* __restrict__ M2b = M2 + (size_t)n * HWPX;
    const float* __restrict__ I1b = im1 + (size_t)n * 3 * HWPX;
    const float* __restrict__ I2b = im2 + (size_t)n * 3 * HWPX;

    // ---- Phase 1: coalesced tile load ----
#pragma unroll
    for (int k = 0; k < 4; k++) {
        int l  = tid + k * 256;
        int dx = l >> 5;
        int dy = l & 31;
        int g  = (x0 + dx) * IMD + (y0 + dy);
        sA[dx][dy] = Cb0[g];
        sB[dx][dy] = Cb1[g];
        sD[dx][dy] = M1b[g];
        sE[dx][dy] = M2b[g];
    }
    __syncthreads();

    // ---- Phase 2: x-fast compute, immediate owner-private writeback ----
    const int dx = tid & 31;        // lane -> x (gathers coalesced)
    const int wp = tid >> 5;        // warp 0..7

#pragma unroll
    for (int k = 0; k < 4; k++) {
        const int dy = wp + k * 8;
        const float c0 = sA[dx][dy];
        const float c1 = sB[dx][dy];
        const float m1 = sD[dx][dy];
        const float m2 = sE[dx][dy];
        const float xf = (float)(x0 + dx);
        const float yf = (float)(y0 + dy);

        float r0, r1, r2;

        // --- sample im1 at (x + c0, y + c1) ---
        {
            float px = xf + c0, py = yf + c1;
            float fx = floorf(px), cx = ceilf(px);
            float fy = floorf(py), cy = ceilf(py);
            float wfx = 1.0f - (px - fx), wcx = 1.0f - (cx - px);
            float wfy = 1.0f - (py - fy), wcy = 1.0f - (cy - py);
            int i00 = (int)fx + IMD * (int)fy;
            int i10 = (int)cx + IMD * (int)fy;
            int i01 = (int)fx + IMD * (int)cy;
            int i11 = (int)cx + IMD * (int)cy;
            i00 = min(max(i00, 0), HWPX - 1);
            i10 = min(max(i10, 0), HWPX - 1);
            i01 = min(max(i01, 0), HWPX - 1);
            i11 = min(max(i11, 0), HWPX - 1);
            float w00 = wfx * wfy, w10 = wcx * wfy;
            float w01 = wfx * wcy, w11 = wcx * wcy;
            const float* p0 = I1b;
            const float* p1 = I1b + HWPX;
            const float* p2 = I1b + 2 * HWPX;
            r0 = (((w00 * __ldg(p0 + i00) + w10 * __ldg(p0 + i10))
                  + w01 * __ldg(p0 + i01)) + w11 * __ldg(p0 + i11)) * m1;
            r1 = (((w00 * __ldg(p1 + i00) + w10 * __ldg(p1 + i10))
                  + w01 * __ldg(p1 + i01)) + w11 * __ldg(p1 + i11)) * m1;
            r2 = (((w00 * __ldg(p2 + i00) + w10 * __ldg(p2 + i10))
                  + w01 * __ldg(p2 + i01)) + w11 * __ldg(p2 + i11)) * m1;
        }
        // --- sample im2 at (x - c0, y - c1) ---
        {
            float px = xf - c0, py = yf - c1;
            float fx = floorf(px), cx = ceilf(px);
            float fy = floorf(py), cy = ceilf(py);
            float wfx = 1.0f - (px - fx), wcx = 1.0f - (cx - px);
            float wfy = 1.0f - (py - fy), wcy = 1.0f - (cy - py);
            int i00 = (int)fx + IMD * (int)fy;
            int i10 = (int)cx + IMD * (int)fy;
            int i01 = (int)fx + IMD * (int)cy;
            int i11 = (int)cx + IMD * (int)cy;
            i00 = min(max(i00, 0), HWPX - 1);
            i10 = min(max(i10, 0), HWPX - 1);
            i01 = min(max(i01, 0), HWPX - 1);
            i11 = min(max(i11, 0), HWPX - 1);
            float w00 = wfx * wfy, w10 = wcx * wfy;
            float w01 = wfx * wcy, w11 = wcx * wcy;
            const float* p0 = I2b;
            const float* p1 = I2b + HWPX;
            const float* p2 = I2b + 2 * HWPX;
            r0 += (((w00 * __ldg(p0 + i00) + w10 * __ldg(p0 + i10))
                   + w01 * __ldg(p0 + i01)) + w11 * __ldg(p0 + i11)) * m2;
            r1 += (((w00 * __ldg(p1 + i00) + w10 * __ldg(p1 + i10))
                   + w01 * __ldg(p1 + i01)) + w11 * __ldg(p1 + i11)) * m2;
            r2 += (((w00 * __ldg(p2 + i00) + w10 * __ldg(p2 + i10))
                   + w01 * __ldg(p2 + i01)) + w11 * __ldg(p2 + i11)) * m2;
        }

        // Owner-private cells: safe to overwrite without a barrier.
        sA[dx][dy] = r0;
        sB[dx][dy] = r1;
        sD[dx][dy] = r2;
    }
    __syncthreads();

    // ---- Phase 3: coalesced store ----
    float* __restrict__ ob = out + (size_t)n * 3 * HWPX;
#pragma unroll
    for (int k = 0; k < 4; k++) {
        int l   = tid + k * 256;
        int ddx = l >> 5;
        int ddy = l & 31;
        int g   = (x0 + ddx) * IMD + (y0 + ddy);
        ob[g]            = sA[ddx][ddy];
        ob[HWPX + g]     = sB[ddx][ddy];
        ob[2 * HWPX + g] = sD[ddx][ddy];
    }
}

extern "C" void kernel_launch(void* const* d_in, const int* in_sizes, int n_in,
                              void* d_out, int out_size)
{
    const float* im1 = (const float*)d_in[0];
    const float* im2 = (const float*)d_in[1];
    const float* C   = (const float*)d_in[2];
    const float* M1  = (const float*)d_in[3];
    const float* M2  = (const float*)d_in[4];
    float* out = (float*)d_out;

    dim3 grid(IMD / 32, IMD / 32, 64);  // (7, 7, 64)
    vm_kernel<<<grid, 256>>>(im1, im2, C, M1, M2, out);
}

// round 5
// speedup vs baseline: 1.2224x; 1.0559x over previous
#include <cuda_runtime.h>

#define IMD 224
#define HWPX (IMD * IMD)

// Tile: 32 x-values (slow dim of p) x 32 y-values (fast dim).
// Phase 1: float4-vectorized coalesced loads of C0,C1,M1,M2 into padded smem.
// Phase 2: threads remapped x-fast so gather index ind = nx + 224*ny is
//          coalesced across the warp; results written straight back to the
//          owner-private smem cells per k-slice.
// Phase 3: float4-vectorized coalesced stores.
__global__ __launch_bounds__(256, 5) void vm_kernel(
    const float* __restrict__ im1, const float* __restrict__ im2,
    const float* __restrict__ C,   const float* __restrict__ M1,
    const float* __restrict__ M2,  float* __restrict__ out)
{
    __shared__ float sA[32][33];  // C0  -> out c0
    __shared__ float sB[32][33];  // C1  -> out c1
    __shared__ float sD[32][33];  // M1  -> out c2
    __shared__ float sE[32][33];  // M2

    const int tid = threadIdx.x;
    const int n  = blockIdx.z;
    const int x0 = blockIdx.y * 32;
    const int y0 = blockIdx.x * 32;

    const float* __restrict__ Cb0 = C  + (size_t)n * 2 * HWPX;
    const float* __restrict__ Cb1 = Cb0 + HWPX;
    const float* __restrict__ M1b = M1 + (size_t)n * HWPX;
    const float* __restrict__ M2b = M2 + (size_t)n * HWPX;
    const float* __restrict__ I1b = im1 + (size_t)n * 3 * HWPX;
    const float* __restrict__ I2b = im2 + (size_t)n * 3 * HWPX;

    // ---- Phase 1: vectorized coalesced tile load ----
    {
        const int pdx = tid >> 3;          // 0..31
        const int pdy = (tid & 7) * 4;     // 0,4,...,28
        const int g   = (x0 + pdx) * IMD + (y0 + pdy);   // 16B aligned
        float4 a = *(const float4*)(Cb0 + g);
        float4 b = *(const float4*)(Cb1 + g);
        float4 d = *(const float4*)(M1b + g);
        float4 e = *(const float4*)(M2b + g);
        sA[pdx][pdy] = a.x; sA[pdx][pdy+1] = a.y; sA[pdx][pdy+2] = a.z; sA[pdx][pdy+3] = a.w;
        sB[pdx][pdy] = b.x; sB[pdx][pdy+1] = b.y; sB[pdx][pdy+2] = b.z; sB[pdx][pdy+3] = b.w;
        sD[pdx][pdy] = d.x; sD[pdx][pdy+1] = d.y; sD[pdx][pdy+2] = d.z; sD[pdx][pdy+3] = d.w;
        sE[pdx][pdy] = e.x; sE[pdx][pdy+1] = e.y; sE[pdx][pdy+2] = e.z; sE[pdx][pdy+3] = e.w;
    }
    __syncthreads();

    // ---- Phase 2: x-fast compute, immediate owner-private writeback ----
    const int dx = tid & 31;        // lane -> x (gathers coalesced)
    const int wp = tid >> 5;        // warp 0..7

#pragma unroll
    for (int k = 0; k < 4; k++) {
        const int dy = wp + k * 8;
        const float c0 = sA[dx][dy];
        const float c1 = sB[dx][dy];
        const float m1 = sD[dx][dy];
        const float m2 = sE[dx][dy];
        const float xf = (float)(x0 + dx);
        const float yf = (float)(y0 + dy);

        float r0, r1, r2;

        // --- sample im1 at (x + c0, y + c1) ---
        {
            float px = xf + c0, py = yf + c1;
            float fx = floorf(px), cx = ceilf(px);
            float fy = floorf(py), cy = ceilf(py);
            float wfx = 1.0f - (px - fx), wcx = 1.0f - (cx - px);
            float wfy = 1.0f - (py - fy), wcy = 1.0f - (cy - py);
            int i00 = (int)fx + IMD * (int)fy;
            int i10 = (int)cx + IMD * (int)fy;
            int i01 = (int)fx + IMD * (int)cy;
            int i11 = (int)cx + IMD * (int)cy;
            i00 = min(max(i00, 0), HWPX - 1);
            i10 = min(max(i10, 0), HWPX - 1);
            i01 = min(max(i01, 0), HWPX - 1);
            i11 = min(max(i11, 0), HWPX - 1);
            float w00 = wfx * wfy, w10 = wcx * wfy;
            float w01 = wfx * wcy, w11 = wcx * wcy;
            const float* p0 = I1b;
            const float* p1 = I1b + HWPX;
            const float* p2 = I1b + 2 * HWPX;
            r0 = (((w00 * __ldg(p0 + i00) + w10 * __ldg(p0 + i10))
                  + w01 * __ldg(p0 + i01)) + w11 * __ldg(p0 + i11)) * m1;
            r1 = (((w00 * __ldg(p1 + i00) + w10 * __ldg(p1 + i10))
                  + w01 * __ldg(p1 + i01)) + w11 * __ldg(p1 + i11)) * m1;
            r2 = (((w00 * __ldg(p2 + i00) + w10 * __ldg(p2 + i10))
                  + w01 * __ldg(p2 + i01)) + w11 * __ldg(p2 + i11)) * m1;
        }
        // --- sample im2 at (x - c0, y - c1) ---
        {
            float px = xf - c0, py = yf - c1;
            float fx = floorf(px), cx = ceilf(px);
            float fy = floorf(py), cy = ceilf(py);
            float wfx = 1.0f - (px - fx), wcx = 1.0f - (cx - px);
            float wfy = 1.0f - (py - fy), wcy = 1.0f - (cy - py);
            int i00 = (int)fx + IMD * (int)fy;
            int i10 = (int)cx + IMD * (int)fy;
            int i01 = (int)fx + IMD * (int)cy;
            int i11 = (int)cx + IMD * (int)cy;
            i00 = min(max(i00, 0), HWPX - 1);
            i10 = min(max(i10, 0), HWPX - 1);
            i01 = min(max(i01, 0), HWPX - 1);
            i11 = min(max(i11, 0), HWPX - 1);
            float w00 = wfx * wfy, w10 = wcx * wfy;
            float w01 = wfx * wcy, w11 = wcx * wcy;
            const float* p0 = I2b;
            const float* p1 = I2b + HWPX;
            const float* p2 = I2b + 2 * HWPX;
            r0 += (((w00 * __ldg(p0 + i00) + w10 * __ldg(p0 + i10))
                   + w01 * __ldg(p0 + i01)) + w11 * __ldg(p0 + i11)) * m2;
            r1 += (((w00 * __ldg(p1 + i00) + w10 * __ldg(p1 + i10))
                   + w01 * __ldg(p1 + i01)) + w11 * __ldg(p1 + i11)) * m2;
            r2 += (((w00 * __ldg(p2 + i00) + w10 * __ldg(p2 + i10))
                   + w01 * __ldg(p2 + i01)) + w11 * __ldg(p2 + i11)) * m2;
        }

        // Owner-private cells: safe to overwrite without a barrier.
        sA[dx][dy] = r0;
        sB[dx][dy] = r1;
        sD[dx][dy] = r2;
    }
    __syncthreads();

    // ---- Phase 3: vectorized coalesced store ----
    {
        float* __restrict__ ob = out + (size_t)n * 3 * HWPX;
        const int pdx = tid >> 3;
        const int pdy = (tid & 7) * 4;
        const int g   = (x0 + pdx) * IMD + (y0 + pdy);   // 16B aligned
        float4 v;
        v.x = sA[pdx][pdy]; v.y = sA[pdx][pdy+1]; v.z = sA[pdx][pdy+2]; v.w = sA[pdx][pdy+3];
        *(float4*)(ob + g) = v;
        v.x = sB[pdx][pdy]; v.y = sB[pdx][pdy+1]; v.z = sB[pdx][pdy+2]; v.w = sB[pdx][pdy+3];
        *(float4*)(ob + HWPX + g) = v;
        v.x = sD[pdx][pdy]; v.y = sD[pdx][pdy+1]; v.z = sD[pdx][pdy+2]; v.w = sD[pdx][pdy+3];
        *(float4*)(ob + 2 * HWPX + g) = v;
    }
}

extern "C" void kernel_launch(void* const* d_in, const int* in_sizes, int n_in,
                              void* d_out, int out_size)
{
    const float* im1 = (const float*)d_in[0];
    const float* im2 = (const float*)d_in[1];
    const float* C   = (const float*)d_in[2];
    const float* M1  = (const float*)d_in[3];
    const float* M2  = (const float*)d_in[4];
    float* out = (float*)d_out;

    dim3 grid(IMD / 32, IMD / 32, 64);  // (7, 7, 64)
    vm_kernel<<<grid, 256>>>(im1, im2, C, M1, M2, out);
}